// round 4
// baseline (speedup 1.0000x reference)
#include <cuda_runtime.h>

#define BATCH 8
#define CHAN  256
#define HH    512
#define WW    512
#define KPOOL 16
#define PH    (HH / KPOOL)     // 32 pooled rows
#define PW    (WW / KPOOL)     // 32 pooled cols
#define NWARPS 8
#define NHALF 2                // image split into 2 half-image blocks
#define STRIPS (PH / NHALF / NWARPS)  // 2 pooled rows per warp per block
#define NSLOTS (BATCH * NHALF)        // partial slots per channel
#define NCELLS ((double)(BATCH * PH * PW))  // 8192

// Per-(channel, batch, half) partial stats: [CHAN][BATCH][NHALF][5]
__device__ float g_stats[CHAN * NSLOTS * 5];

__global__ void __launch_bounds__(256, 4) pool_stats_kernel(
    const float* __restrict__ f1, const float* __restrict__ f2)
{
    const int idx  = blockIdx.x;          // = bc*2 + half
    const int bc   = idx >> 1;            // b*CHAN + c  (memory order)
    const int half = idx & 1;
    const int c    = bc & (CHAN - 1);
    const int b    = bc >> 8;
    const int wid  = threadIdx.x >> 5;
    const int lane = threadIdx.x & 31;

    const size_t base = (size_t)bc * HH * WW;
    const float4* __restrict__ p1 = (const float4*)(f1 + base);
    const float4* __restrict__ p2 = (const float4*)(f2 + base);
    const int row_f4 = WW / 4;            // 128 float4 per row

    float s1 = 0.f, s2 = 0.f, s11 = 0.f, s22 = 0.f, s12 = 0.f;

    #pragma unroll
    for (int strip = 0; strip < STRIPS; ++strip) {
        // pooled rows: this block owns [half*16, half*16+16); warp gets 2
        const int prow = half * (PH / NHALF) + wid * STRIPS + strip;
        const int row0 = prow * KPOOL;

        float4 a1[4], a2[4];
        #pragma unroll
        for (int it = 0; it < 4; ++it) {
            a1[it] = make_float4(0.f, 0.f, 0.f, 0.f);
            a2[it] = make_float4(0.f, 0.f, 0.f, 0.f);
        }

        for (int r = 0; r < KPOOL; ++r) {
            const size_t roff = (size_t)(row0 + r) * row_f4;
            #pragma unroll
            for (int it = 0; it < 4; ++it) {
                const float4 v1 = __ldcs(&p1[roff + it * 32 + lane]);
                const float4 v2 = __ldcs(&p2[roff + it * 32 + lane]);
                a1[it].x += v1.x; a1[it].y += v1.y; a1[it].z += v1.z; a1[it].w += v1.w;
                a2[it].x += v2.x; a2[it].y += v2.y; a2[it].z += v2.z; a2[it].w += v2.w;
            }
        }

        #pragma unroll
        for (int it = 0; it < 4; ++it) {
            // 4 consecutive lanes cover one 16-col pooled cell
            float t1 = (a1[it].x + a1[it].y) + (a1[it].z + a1[it].w);
            float t2 = (a2[it].x + a2[it].y) + (a2[it].z + a2[it].w);
            t1 += __shfl_xor_sync(0xffffffffu, t1, 1);
            t1 += __shfl_xor_sync(0xffffffffu, t1, 2);
            t2 += __shfl_xor_sync(0xffffffffu, t2, 1);
            t2 += __shfl_xor_sync(0xffffffffu, t2, 2);
            if ((lane & 3) == 0) {
                const float q1 = t1 * (1.0f / 256.0f);  // pooled mean
                const float q2 = t2 * (1.0f / 256.0f);
                s1  += q1;       s2  += q2;
                s11 += q1 * q1;  s22 += q2 * q2;
                s12 += q1 * q2;
            }
        }
    }

    // warp reduce the 5 sums
    #pragma unroll
    for (int off = 16; off > 0; off >>= 1) {
        s1  += __shfl_xor_sync(0xffffffffu, s1,  off);
        s2  += __shfl_xor_sync(0xffffffffu, s2,  off);
        s11 += __shfl_xor_sync(0xffffffffu, s11, off);
        s22 += __shfl_xor_sync(0xffffffffu, s22, off);
        s12 += __shfl_xor_sync(0xffffffffu, s12, off);
    }

    __shared__ float sh[NWARPS][5];
    if (lane == 0) {
        sh[wid][0] = s1;  sh[wid][1] = s2;
        sh[wid][2] = s11; sh[wid][3] = s22; sh[wid][4] = s12;
    }
    __syncthreads();

    if (threadIdx.x == 0) {
        float t0 = 0.f, t1 = 0.f, t2 = 0.f, t3 = 0.f, t4 = 0.f;
        #pragma unroll
        for (int w = 0; w < NWARPS; ++w) {
            t0 += sh[w][0]; t1 += sh[w][1]; t2 += sh[w][2];
            t3 += sh[w][3]; t4 += sh[w][4];
        }
        // slot = ((c*BATCH + b)*NHALF + half)
        float* dst = &g_stats[(((c * BATCH) + b) * NHALF + half) * 5];
        dst[0] = t0; dst[1] = t1; dst[2] = t2; dst[3] = t3; dst[4] = t4;
    }
}

__global__ void __launch_bounds__(256) finalize_kernel(float* __restrict__ out)
{
    const int c = threadIdx.x;   // one thread per channel
    double s1 = 0.0, s2 = 0.0, s11 = 0.0, s22 = 0.0, s12 = 0.0;
    #pragma unroll
    for (int k = 0; k < NSLOTS; ++k) {
        const float* p = &g_stats[(c * NSLOTS + k) * 5];
        s1 += p[0]; s2 += p[1]; s11 += p[2]; s22 += p[3]; s12 += p[4];
    }
    const double n  = NCELLS;
    const double m1 = s1 / n;
    const double m2 = s2 / n;
    const double cov  = s12 / n - m1 * m2;                  // biased (torch.mean)
    const double var1 = (s11 - n * m1 * m1) / (n - 1.0);    // unbiased (torch.std)
    const double var2 = (s22 - n * m2 * m2) / (n - 1.0);
    const double std1 = sqrt(var1 > 0.0 ? var1 : 0.0);
    const double std2 = sqrt(var2 > 0.0 ? var2 : 0.0);
    const double corr = cov / (std1 * std2 + 1e-8);

    __shared__ double sh[CHAN];
    sh[c] = fabs(corr);
    __syncthreads();
    #pragma unroll
    for (int s = CHAN / 2; s > 0; s >>= 1) {
        if (c < s) sh[c] += sh[c + s];
        __syncthreads();
    }
    if (c == 0) out[0] = (float)(1.0 - sh[0] / (double)CHAN);
}

extern "C" void kernel_launch(void* const* d_in, const int* in_sizes, int n_in,
                              void* d_out, int out_size)
{
    const float* f1 = (const float*)d_in[0];
    const float* f2 = (const float*)d_in[1];
    float* out = (float*)d_out;

    pool_stats_kernel<<<BATCH * CHAN * NHALF, 256>>>(f1, f2);
    finalize_kernel<<<1, 256>>>(out);
}

// round 5
// speedup vs baseline: 1.0214x; 1.0214x over previous
#include <cuda_runtime.h>

#define BATCH 8
#define CHAN  256
#define HH    512
#define WW    512
#define KPOOL 16
#define PH    (HH / KPOOL)   // 32 pooled rows
#define PW    (WW / KPOOL)   // 32 pooled cols
#define NWARPS 8
#define STRIPS (PH / NWARPS) // 4 pooled rows per warp
#define IMGS_PER_BLOCK 4
#define NBLOCKS (BATCH * CHAN / IMGS_PER_BLOCK)   // 512 — single wave at 4 CTAs/SM
#define NCELLS ((double)(BATCH * PH * PW))        // 8192

// Per-(channel,batch) partial stats: [CHAN][BATCH][5] = {s1,s2,s11,s22,s12}
__device__ float g_stats[CHAN * BATCH * 5];

__global__ void __launch_bounds__(256, 4) pool_stats_kernel(
    const float* __restrict__ f1, const float* __restrict__ f2)
{
    const int wid  = threadIdx.x >> 5;
    const int lane = threadIdx.x & 31;
    const int bc0  = blockIdx.x * IMGS_PER_BLOCK;
    const int row_f4 = WW / 4;            // 128 float4 per row

    __shared__ float sh[IMGS_PER_BLOCK][NWARPS][5];

    #pragma unroll 1
    for (int img = 0; img < IMGS_PER_BLOCK; ++img) {
        const int bc = bc0 + img;         // = b*CHAN + c  (memory order)
        const size_t base = (size_t)bc * HH * WW;
        const float4* __restrict__ p1 = (const float4*)(f1 + base);
        const float4* __restrict__ p2 = (const float4*)(f2 + base);

        float s1 = 0.f, s2 = 0.f, s11 = 0.f, s22 = 0.f, s12 = 0.f;

        #pragma unroll 1
        for (int strip = 0; strip < STRIPS; ++strip) {
            const int prow = wid * STRIPS + strip;   // pooled row 0..31
            const int row0 = prow * KPOOL;

            float4 a1[4], a2[4];
            #pragma unroll
            for (int it = 0; it < 4; ++it) {
                a1[it] = make_float4(0.f, 0.f, 0.f, 0.f);
                a2[it] = make_float4(0.f, 0.f, 0.f, 0.f);
            }

            for (int r = 0; r < KPOOL; ++r) {
                const size_t roff = (size_t)(row0 + r) * row_f4;
                #pragma unroll
                for (int it = 0; it < 4; ++it) {
                    const float4 v1 = __ldg(&p1[roff + it * 32 + lane]);
                    const float4 v2 = __ldg(&p2[roff + it * 32 + lane]);
                    a1[it].x += v1.x; a1[it].y += v1.y; a1[it].z += v1.z; a1[it].w += v1.w;
                    a2[it].x += v2.x; a2[it].y += v2.y; a2[it].z += v2.z; a2[it].w += v2.w;
                }
            }

            #pragma unroll
            for (int it = 0; it < 4; ++it) {
                // 4 consecutive lanes cover one 16-col pooled cell
                float t1 = (a1[it].x + a1[it].y) + (a1[it].z + a1[it].w);
                float t2 = (a2[it].x + a2[it].y) + (a2[it].z + a2[it].w);
                t1 += __shfl_xor_sync(0xffffffffu, t1, 1);
                t1 += __shfl_xor_sync(0xffffffffu, t1, 2);
                t2 += __shfl_xor_sync(0xffffffffu, t2, 1);
                t2 += __shfl_xor_sync(0xffffffffu, t2, 2);
                if ((lane & 3) == 0) {
                    const float q1 = t1 * (1.0f / 256.0f);  // pooled mean
                    const float q2 = t2 * (1.0f / 256.0f);
                    s1  += q1;       s2  += q2;
                    s11 += q1 * q1;  s22 += q2 * q2;
                    s12 += q1 * q2;
                }
            }
        }

        // warp reduce the 5 sums
        #pragma unroll
        for (int off = 16; off > 0; off >>= 1) {
            s1  += __shfl_xor_sync(0xffffffffu, s1,  off);
            s2  += __shfl_xor_sync(0xffffffffu, s2,  off);
            s11 += __shfl_xor_sync(0xffffffffu, s11, off);
            s22 += __shfl_xor_sync(0xffffffffu, s22, off);
            s12 += __shfl_xor_sync(0xffffffffu, s12, off);
        }
        if (lane == 0) {
            sh[img][wid][0] = s1;  sh[img][wid][1] = s2;
            sh[img][wid][2] = s11; sh[img][wid][3] = s22; sh[img][wid][4] = s12;
        }
        // no syncthreads needed between images: each image uses its own sh slice
    }

    __syncthreads();

    // 4 threads each finish one image's 8-warp reduction and write its slot
    if (threadIdx.x < IMGS_PER_BLOCK) {
        const int img = threadIdx.x;
        const int bc  = bc0 + img;
        const int c   = bc & (CHAN - 1);
        const int b   = bc >> 8;
        float t0 = 0.f, t1 = 0.f, t2 = 0.f, t3 = 0.f, t4 = 0.f;
        #pragma unroll
        for (int w = 0; w < NWARPS; ++w) {
            t0 += sh[img][w][0]; t1 += sh[img][w][1]; t2 += sh[img][w][2];
            t3 += sh[img][w][3]; t4 += sh[img][w][4];
        }
        float* dst = &g_stats[(c * BATCH + b) * 5];
        dst[0] = t0; dst[1] = t1; dst[2] = t2; dst[3] = t3; dst[4] = t4;
    }
}

__global__ void __launch_bounds__(256) finalize_kernel(float* __restrict__ out)
{
    const int c = threadIdx.x;   // one thread per channel
    double s1 = 0.0, s2 = 0.0, s11 = 0.0, s22 = 0.0, s12 = 0.0;
    #pragma unroll
    for (int b = 0; b < BATCH; ++b) {
        const float* p = &g_stats[(c * BATCH + b) * 5];
        s1 += p[0]; s2 += p[1]; s11 += p[2]; s22 += p[3]; s12 += p[4];
    }
    const double n  = NCELLS;
    const double m1 = s1 / n;
    const double m2 = s2 / n;
    const double cov  = s12 / n - m1 * m2;                  // biased (torch.mean)
    const double var1 = (s11 - n * m1 * m1) / (n - 1.0);    // unbiased (torch.std)
    const double var2 = (s22 - n * m2 * m2) / (n - 1.0);
    const double std1 = sqrt(var1 > 0.0 ? var1 : 0.0);
    const double std2 = sqrt(var2 > 0.0 ? var2 : 0.0);
    const double corr = cov / (std1 * std2 + 1e-8);

    __shared__ double sh[CHAN];
    sh[c] = fabs(corr);
    __syncthreads();
    #pragma unroll
    for (int s = CHAN / 2; s > 0; s >>= 1) {
        if (c < s) sh[c] += sh[c + s];
        __syncthreads();
    }
    if (c == 0) out[0] = (float)(1.0 - sh[0] / (double)CHAN);
}

extern "C" void kernel_launch(void* const* d_in, const int* in_sizes, int n_in,
                              void* d_out, int out_size)
{
    const float* f1 = (const float*)d_in[0];
    const float* f2 = (const float*)d_in[1];
    float* out = (float*)d_out;

    pool_stats_kernel<<<NBLOCKS, 256>>>(f1, f2);
    finalize_kernel<<<1, 256>>>(out);
}

// round 6
// speedup vs baseline: 1.0510x; 1.0291x over previous
#include <cuda_runtime.h>

#define BATCH 8
#define CHAN  256
#define HH    512
#define WW    512
#define KPOOL 16
#define PH    (HH / KPOOL)   // 32 pooled rows
#define PW    (WW / KPOOL)   // 32 pooled cols
#define NWARPS 8
#define STRIPS (PH / NWARPS) // 4 pooled rows per warp
#define NCELLS 8192.0f       // BATCH * PH * PW

// Per-(channel,batch) partial stats: [CHAN][BATCH][5] = {s1,s2,s11,s22,s12}
__device__ float g_stats[CHAN * BATCH * 5];

// ---------- streaming kernel: identical to the proven 616us R1 version ----------
__global__ void __launch_bounds__(256, 4) pool_stats_kernel(
    const float* __restrict__ f1, const float* __restrict__ f2)
{
    const int bc   = blockIdx.x;          // = b*CHAN + c  (matches memory order)
    const int c    = bc & (CHAN - 1);
    const int b    = bc >> 8;
    const int wid  = threadIdx.x >> 5;
    const int lane = threadIdx.x & 31;

    const size_t base = (size_t)bc * HH * WW;
    const float4* __restrict__ p1 = (const float4*)(f1 + base);
    const float4* __restrict__ p2 = (const float4*)(f2 + base);
    const int row_f4 = WW / 4;            // 128 float4 per row

    float s1 = 0.f, s2 = 0.f, s11 = 0.f, s22 = 0.f, s12 = 0.f;

    for (int strip = 0; strip < STRIPS; ++strip) {
        const int prow = wid * STRIPS + strip;   // pooled row 0..31
        const int row0 = prow * KPOOL;

        float4 a1[4], a2[4];
        #pragma unroll
        for (int it = 0; it < 4; ++it) {
            a1[it] = make_float4(0.f, 0.f, 0.f, 0.f);
            a2[it] = make_float4(0.f, 0.f, 0.f, 0.f);
        }

        for (int r = 0; r < KPOOL; ++r) {
            const size_t roff = (size_t)(row0 + r) * row_f4;
            #pragma unroll
            for (int it = 0; it < 4; ++it) {
                const float4 v1 = __ldg(&p1[roff + it * 32 + lane]);
                const float4 v2 = __ldg(&p2[roff + it * 32 + lane]);
                a1[it].x += v1.x; a1[it].y += v1.y; a1[it].z += v1.z; a1[it].w += v1.w;
                a2[it].x += v2.x; a2[it].y += v2.y; a2[it].z += v2.z; a2[it].w += v2.w;
            }
        }

        #pragma unroll
        for (int it = 0; it < 4; ++it) {
            // 4 consecutive lanes cover one 16-col pooled cell
            float t1 = (a1[it].x + a1[it].y) + (a1[it].z + a1[it].w);
            float t2 = (a2[it].x + a2[it].y) + (a2[it].z + a2[it].w);
            t1 += __shfl_xor_sync(0xffffffffu, t1, 1);
            t1 += __shfl_xor_sync(0xffffffffu, t1, 2);
            t2 += __shfl_xor_sync(0xffffffffu, t2, 1);
            t2 += __shfl_xor_sync(0xffffffffu, t2, 2);
            if ((lane & 3) == 0) {
                const float q1 = t1 * (1.0f / 256.0f);  // pooled mean
                const float q2 = t2 * (1.0f / 256.0f);
                s1  += q1;       s2  += q2;
                s11 += q1 * q1;  s22 += q2 * q2;
                s12 += q1 * q2;
            }
        }
    }

    // warp reduce the 5 sums
    #pragma unroll
    for (int off = 16; off > 0; off >>= 1) {
        s1  += __shfl_xor_sync(0xffffffffu, s1,  off);
        s2  += __shfl_xor_sync(0xffffffffu, s2,  off);
        s11 += __shfl_xor_sync(0xffffffffu, s11, off);
        s22 += __shfl_xor_sync(0xffffffffu, s22, off);
        s12 += __shfl_xor_sync(0xffffffffu, s12, off);
    }

    __shared__ float sh[NWARPS][5];
    if (lane == 0) {
        sh[wid][0] = s1;  sh[wid][1] = s2;
        sh[wid][2] = s11; sh[wid][3] = s22; sh[wid][4] = s12;
    }
    __syncthreads();

    if (threadIdx.x == 0) {
        float t0 = 0.f, t1 = 0.f, t2 = 0.f, t3 = 0.f, t4 = 0.f;
        #pragma unroll
        for (int w = 0; w < NWARPS; ++w) {
            t0 += sh[w][0]; t1 += sh[w][1]; t2 += sh[w][2];
            t3 += sh[w][3]; t4 += sh[w][4];
        }
        float* dst = &g_stats[(c * BATCH + b) * 5];
        dst[0] = t0; dst[1] = t1; dst[2] = t2; dst[3] = t3; dst[4] = t4;
    }
}

// ---------- lightweight finalize: float math, shuffle reduce, 1 syncthreads ----------
__global__ void __launch_bounds__(256) finalize_kernel(float* __restrict__ out)
{
    const int c    = threadIdx.x;        // one thread per channel
    const int lane = c & 31;
    const int wid  = c >> 5;

    // 40 contiguous floats per channel -> 40 independent L2-hit loads in flight
    float v[40];
    const float* p = &g_stats[c * BATCH * 5];
    #pragma unroll
    for (int i = 0; i < 40; ++i) v[i] = p[i];

    float s1 = 0.f, s2 = 0.f, s11 = 0.f, s22 = 0.f, s12 = 0.f;
    #pragma unroll
    for (int b = 0; b < BATCH; ++b) {
        s1  += v[b * 5 + 0];
        s2  += v[b * 5 + 1];
        s11 += v[b * 5 + 2];
        s22 += v[b * 5 + 3];
        s12 += v[b * 5 + 4];
    }

    const float n    = NCELLS;
    const float rn   = 1.0f / n;
    const float m1   = s1 * rn;
    const float m2   = s2 * rn;
    const float cov  = s12 * rn - m1 * m2;                      // biased (torch.mean)
    const float var1 = (s11 - n * m1 * m1) * (1.0f / (n - 1.0f)); // unbiased (torch.std)
    const float var2 = (s22 - n * m2 * m2) * (1.0f / (n - 1.0f));
    const float std1 = sqrtf(fmaxf(var1, 0.0f));
    const float std2 = sqrtf(fmaxf(var2, 0.0f));
    float ac = fabsf(cov / (std1 * std2 + 1e-8f));

    // warp reduce |corr|
    #pragma unroll
    for (int off = 16; off > 0; off >>= 1)
        ac += __shfl_xor_sync(0xffffffffu, ac, off);

    __shared__ float shw[8];
    if (lane == 0) shw[wid] = ac;
    __syncthreads();

    if (threadIdx.x == 0) {
        float t = 0.f;
        #pragma unroll
        for (int w = 0; w < 8; ++w) t += shw[w];
        out[0] = 1.0f - t * (1.0f / (float)CHAN);
    }
}

extern "C" void kernel_launch(void* const* d_in, const int* in_sizes, int n_in,
                              void* d_out, int out_size)
{
    const float* f1 = (const float*)d_in[0];
    const float* f2 = (const float*)d_in[1];
    float* out = (float*)d_out;

    pool_stats_kernel<<<BATCH * CHAN, 256>>>(f1, f2);
    finalize_kernel<<<1, 256>>>(out);
}

// round 7
// speedup vs baseline: 1.0702x; 1.0182x over previous
#include <cuda_runtime.h>

#define BATCH 8
#define CHAN  256
#define HH    512
#define WW    512
#define KPOOL 16
#define PH    (HH / KPOOL)   // 32 pooled rows
#define PW    (WW / KPOOL)   // 32 pooled cols
#define NWARPS 8
#define STRIPS (PH / NWARPS) // 4 pooled rows per warp
#define NCELLS 8192.0f       // BATCH * PH * PW

// Per-(channel,batch) partial stats: [CHAN][BATCH][5] = {s1,s2,s11,s22,s12}
__device__ float g_stats[CHAN * BATCH * 5];

// ---------- streaming kernel: proven 608us geometry, + PDL trigger ----------
__global__ void __launch_bounds__(256, 4) pool_stats_kernel(
    const float* __restrict__ f1, const float* __restrict__ f2)
{
    const int bc   = blockIdx.x;          // = b*CHAN + c  (matches memory order)
    const int c    = bc & (CHAN - 1);
    const int b    = bc >> 8;
    const int wid  = threadIdx.x >> 5;
    const int lane = threadIdx.x & 31;

    const size_t base = (size_t)bc * HH * WW;
    const float4* __restrict__ p1 = (const float4*)(f1 + base);
    const float4* __restrict__ p2 = (const float4*)(f2 + base);
    const int row_f4 = WW / 4;            // 128 float4 per row

    float s1 = 0.f, s2 = 0.f, s11 = 0.f, s22 = 0.f, s12 = 0.f;

    for (int strip = 0; strip < STRIPS; ++strip) {
        const int prow = wid * STRIPS + strip;   // pooled row 0..31
        const int row0 = prow * KPOOL;

        float4 a1[4], a2[4];
        #pragma unroll
        for (int it = 0; it < 4; ++it) {
            a1[it] = make_float4(0.f, 0.f, 0.f, 0.f);
            a2[it] = make_float4(0.f, 0.f, 0.f, 0.f);
        }

        for (int r = 0; r < KPOOL; ++r) {
            const size_t roff = (size_t)(row0 + r) * row_f4;
            #pragma unroll
            for (int it = 0; it < 4; ++it) {
                const float4 v1 = __ldg(&p1[roff + it * 32 + lane]);
                const float4 v2 = __ldg(&p2[roff + it * 32 + lane]);
                a1[it].x += v1.x; a1[it].y += v1.y; a1[it].z += v1.z; a1[it].w += v1.w;
                a2[it].x += v2.x; a2[it].y += v2.y; a2[it].z += v2.z; a2[it].w += v2.w;
            }
        }

        #pragma unroll
        for (int it = 0; it < 4; ++it) {
            // 4 consecutive lanes cover one 16-col pooled cell
            float t1 = (a1[it].x + a1[it].y) + (a1[it].z + a1[it].w);
            float t2 = (a2[it].x + a2[it].y) + (a2[it].z + a2[it].w);
            t1 += __shfl_xor_sync(0xffffffffu, t1, 1);
            t1 += __shfl_xor_sync(0xffffffffu, t1, 2);
            t2 += __shfl_xor_sync(0xffffffffu, t2, 1);
            t2 += __shfl_xor_sync(0xffffffffu, t2, 2);
            if ((lane & 3) == 0) {
                const float q1 = t1 * (1.0f / 256.0f);  // pooled mean
                const float q2 = t2 * (1.0f / 256.0f);
                s1  += q1;       s2  += q2;
                s11 += q1 * q1;  s22 += q2 * q2;
                s12 += q1 * q2;
            }
        }
    }

    // warp reduce the 5 sums
    #pragma unroll
    for (int off = 16; off > 0; off >>= 1) {
        s1  += __shfl_xor_sync(0xffffffffu, s1,  off);
        s2  += __shfl_xor_sync(0xffffffffu, s2,  off);
        s11 += __shfl_xor_sync(0xffffffffu, s11, off);
        s22 += __shfl_xor_sync(0xffffffffu, s22, off);
        s12 += __shfl_xor_sync(0xffffffffu, s12, off);
    }

    __shared__ float sh[NWARPS][5];
    if (lane == 0) {
        sh[wid][0] = s1;  sh[wid][1] = s2;
        sh[wid][2] = s11; sh[wid][3] = s22; sh[wid][4] = s12;
    }
    __syncthreads();

    if (threadIdx.x == 0) {
        float t0 = 0.f, t1 = 0.f, t2 = 0.f, t3 = 0.f, t4 = 0.f;
        #pragma unroll
        for (int w = 0; w < NWARPS; ++w) {
            t0 += sh[w][0]; t1 += sh[w][1]; t2 += sh[w][2];
            t3 += sh[w][3]; t4 += sh[w][4];
        }
        float* dst = &g_stats[(c * BATCH + b) * 5];
        dst[0] = t0; dst[1] = t1; dst[2] = t2; dst[3] = t3; dst[4] = t4;

        // Publish this block's stats for the PDL-dependent finalize kernel.
        __threadfence();
        cudaTriggerProgrammaticLaunchCompletion();
    }
}

// ---------- finalize: launched with PDL, overlaps streaming tail ----------
__global__ void __launch_bounds__(256) finalize_kernel(float* __restrict__ out)
{
    // Wait until every pool_stats block has triggered (stats visible).
    cudaGridDependencySynchronize();

    const int c    = threadIdx.x;        // one thread per channel
    const int lane = c & 31;
    const int wid  = c >> 5;

    // 40 contiguous floats per channel -> 40 independent L2-hit loads in flight
    float v[40];
    const float* p = &g_stats[c * BATCH * 5];
    #pragma unroll
    for (int i = 0; i < 40; ++i) v[i] = p[i];

    float s1 = 0.f, s2 = 0.f, s11 = 0.f, s22 = 0.f, s12 = 0.f;
    #pragma unroll
    for (int b = 0; b < BATCH; ++b) {
        s1  += v[b * 5 + 0];
        s2  += v[b * 5 + 1];
        s11 += v[b * 5 + 2];
        s22 += v[b * 5 + 3];
        s12 += v[b * 5 + 4];
    }

    const float n    = NCELLS;
    const float rn   = 1.0f / n;
    const float m1   = s1 * rn;
    const float m2   = s2 * rn;
    const float cov  = s12 * rn - m1 * m2;                        // biased (torch.mean)
    const float var1 = (s11 - n * m1 * m1) * (1.0f / (n - 1.0f)); // unbiased (torch.std)
    const float var2 = (s22 - n * m2 * m2) * (1.0f / (n - 1.0f));
    const float std1 = sqrtf(fmaxf(var1, 0.0f));
    const float std2 = sqrtf(fmaxf(var2, 0.0f));
    float ac = fabsf(cov / (std1 * std2 + 1e-8f));

    // warp reduce |corr|
    #pragma unroll
    for (int off = 16; off > 0; off >>= 1)
        ac += __shfl_xor_sync(0xffffffffu, ac, off);

    __shared__ float shw[8];
    if (lane == 0) shw[wid] = ac;
    __syncthreads();

    if (threadIdx.x == 0) {
        float t = 0.f;
        #pragma unroll
        for (int w = 0; w < 8; ++w) t += shw[w];
        out[0] = 1.0f - t * (1.0f / (float)CHAN);
    }
}

extern "C" void kernel_launch(void* const* d_in, const int* in_sizes, int n_in,
                              void* d_out, int out_size)
{
    const float* f1 = (const float*)d_in[0];
    const float* f2 = (const float*)d_in[1];
    float* out = (float*)d_out;

    pool_stats_kernel<<<BATCH * CHAN, 256>>>(f1, f2);

    // Finalize with programmatic dependent launch: ramps up while the
    // streaming kernel drains, blocks in cudaGridDependencySynchronize().
    cudaLaunchConfig_t cfg = {};
    cfg.gridDim  = dim3(1, 1, 1);
    cfg.blockDim = dim3(256, 1, 1);
    cfg.dynamicSmemBytes = 0;
    cudaLaunchAttribute attr[1];
    attr[0].id = cudaLaunchAttributeProgrammaticStreamSerialization;
    attr[0].val.programmaticStreamSerializationAllowed = 1;
    cfg.attrs = attr;
    cfg.numAttrs = 1;
    cudaLaunchKernelEx(&cfg, finalize_kernel, out);
}